// round 14
// baseline (speedup 1.0000x reference)
#include <cuda_runtime.h>
#include <cuda_bf16.h>
#include <cuda_fp16.h>

#define B_DIM 8
#define N_PTS 2048
#define NPTS_TOTAL (B_DIM * N_PTS)
#define C_OUT 128
#define H_DIM 64
#define NSAMPLE 64
#define R2 0.36f

// Scratch (allocation-free rule: __device__ globals)
__device__ __half g_fh[NPTS_TOTAL * C_OUT];  // per-point features, fp16 (4 MB)
__device__ float4 g_xpad[NPTS_TOTAL];        // (x, y, z, x^2+y^2+z^2)

// ---- packed fp32x2 helpers (sm_100+ FFMA2; numerically identical to FFMA) --
__device__ __forceinline__ unsigned long long ffma2(unsigned long long a,
                                                    unsigned long long b,
                                                    unsigned long long c)
{
    unsigned long long d;
    asm("fma.rn.f32x2 %0, %1, %2, %3;" : "=l"(d) : "l"(a), "l"(b), "l"(c));
    return d;
}
__device__ __forceinline__ unsigned long long bcast2(float h)
{
    unsigned long long d;
    const unsigned hb = __float_as_uint(h);
    asm("mov.b64 %0, {%1, %1};" : "=l"(d) : "r"(hb));
    return d;
}

// ---------------------------------------------------------------------------
// Kernel 1: per-point MLP features. POINT = LANE layout (warp-uniform W2
// broadcasts), packed FFMA2 inner product. (Unchanged from R9.)
// ---------------------------------------------------------------------------
#define SH1_STRIDE 68
#define SW2F_STRIDE 132

__global__ __launch_bounds__(128)
void feat_kernel(const float* __restrict__ x,
                 const float* __restrict__ W1,
                 const float* __restrict__ b1,
                 const float* __restrict__ W2,
                 const float* __restrict__ b2)
{
    __shared__ float sW2f[H_DIM * SW2F_STRIDE];   // [k][c], 33.8 KB
    __shared__ float sh1[32 * SH1_STRIDE];        // [point][row], 8.7 KB
    __shared__ float sW1[H_DIM * 3];
    __shared__ float sb1[H_DIM];
    __shared__ float sb2[C_OUT];

    const int tid = threadIdx.x;
    for (int idx = tid; idx < C_OUT * H_DIM; idx += 128) {
        const int c = idx >> 6, k = idx & 63;
        sW2f[k * SW2F_STRIDE + c] = W2[idx];
    }
    for (int i = tid; i < H_DIM * 3; i += 128) sW1[i] = W1[i];
    for (int i = tid; i < H_DIM;     i += 128) sb1[i] = b1[i];
    for (int i = tid; i < C_OUT;     i += 128) sb2[i] = b2[i];
    __syncthreads();

    const int warpId = tid >> 5;               // channel quarter 0..3
    const int lane   = tid & 31;
    const int p      = blockIdx.x * 32 + lane; // this thread's point

    const float x0 = x[p * 3 + 0];
    const float x1 = x[p * 3 + 1];
    const float x2 = x[p * 3 + 2];
    if (warpId == 0) {
        // match reference: sq = sum(x*x) left-to-right
        float s = x0 * x0;
        s = s + x1 * x1;
        s = s + x2 * x2;
        g_xpad[p] = make_float4(x0, x1, x2, s);
    }

    #pragma unroll
    for (int t = 0; t < 16; t++) {
        const int r = warpId * 16 + t;
        float v = fmaf(sW1[r * 3 + 2], x2,
                  fmaf(sW1[r * 3 + 1], x1, sW1[r * 3 + 0] * x0)) + sb1[r];
        sh1[lane * SH1_STRIDE + r] = fmaxf(v, 0.0f);
    }
    __syncthreads();

    unsigned long long acc[16];
    #pragma unroll
    for (int t = 0; t < 16; t++)
        acc[t] = *reinterpret_cast<const unsigned long long*>(
                     &sb2[warpId * 32 + 2 * t]);

    const float* h1p = &sh1[lane * SH1_STRIDE];
    #pragma unroll 4
    for (int k4 = 0; k4 < 16; k4++) {
        const float4 h = *reinterpret_cast<const float4*>(&h1p[k4 * 4]);
        #pragma unroll
        for (int kk = 0; kk < 4; kk++) {
            const int k = k4 * 4 + kk;
            const unsigned long long hh = bcast2((&h.x)[kk]);
            const float* base = &sW2f[k * SW2F_STRIDE + warpId * 32];
            #pragma unroll
            for (int g = 0; g < 8; g++) {
                const ulonglong2 w =
                    *reinterpret_cast<const ulonglong2*>(base + g * 4);
                acc[2 * g + 0] = ffma2(w.x, hh, acc[2 * g + 0]);
                acc[2 * g + 1] = ffma2(w.y, hh, acc[2 * g + 1]);
            }
        }
    }

    __half* fp = &g_fh[(size_t)p * C_OUT + warpId * 32];
    #pragma unroll
    for (int t = 0; t < 8; t++) {
        unsigned l0, h0, l1, h1v;
        asm("mov.b64 {%0, %1}, %2;" : "=r"(l0), "=r"(h0) : "l"(acc[2 * t + 0]));
        asm("mov.b64 {%0, %1}, %2;" : "=r"(l1), "=r"(h1v) : "l"(acc[2 * t + 1]));
        const float f0 = fmaxf(__uint_as_float(l0), 0.0f);
        const float f1 = fmaxf(__uint_as_float(h0), 0.0f);
        const float f2 = fmaxf(__uint_as_float(l1), 0.0f);
        const float f3 = fmaxf(__uint_as_float(h1v), 0.0f);
        __half2 lo = __floats2half2_rn(f0, f1);
        __half2 hi = __floats2half2_rn(f2, f3);
        uint2 v;
        v.x = *reinterpret_cast<unsigned*>(&lo);
        v.y = *reinterpret_cast<unsigned*>(&hi);
        *reinterpret_cast<uint2*>(fp + t * 4) = v;
    }
}

// ---------------------------------------------------------------------------
// Kernel 2 (fused): 512 threads = 16 warps = 16 consecutive queries.
// __launch_bounds__(512, 3): cap regs ~42 -> 3 blocks/SM (occ 75%).
// Phase 2 restructured for register budget: 2 load chains (was 4); indices
// stored pre-shifted (<<8) so gather addresses need no IMAD.
// ---------------------------------------------------------------------------
__global__ __launch_bounds__(512, 3)
void group_max_kernel(float* __restrict__ out)
{
    __shared__ float4 sxb[N_PTS];            // 32 KB
    __shared__ int    sidx[16][NSAMPLE];     // 4 KB  (byte offsets: p*256)
    __shared__ float  sout[C_OUT][17];       // 8.7 KB

    const int tid  = threadIdx.x;
    const int q    = tid >> 5;               // local query 0..15
    const int lane = tid & 31;

    const int b  = blockIdx.x >> 7;          // 128 blocks per batch
    const int n0 = (blockIdx.x & 127) << 4;
    const int n  = n0 + q;

    // ---- Phase 0: stage coords ----
    const float4* __restrict__ xb = g_xpad + b * N_PTS;
    #pragma unroll
    for (int i = tid; i < N_PTS; i += 512) sxb[i] = xb[i];
    __syncthreads();

    const float4 qc = sxb[n];

    // ---- Phase 1: scan (identical classification arithmetic) ----
    int found = 0;
    for (int pb = 0; pb < N_PTS && found < NSAMPLE; pb += 32) {
        const float4 r = sxb[pb + lane];
        const float dot  = fmaf(qc.z, r.z, fmaf(qc.y, r.y, qc.x * r.x));
        const float dist = (qc.w + r.w) - 2.0f * dot;
        const bool  qual = !(dist > R2);
        const unsigned m = __ballot_sync(0xffffffffu, qual);
        const int need = NSAMPLE - found;
        const int rank = __popc(m & ((1u << lane) - 1u));
        const bool take = qual && (rank < need);
        if (take) sidx[q][found + rank] = (pb + lane) << 8;   // byte offset
        found += __popc(__ballot_sync(0xffffffffu, take));
    }
    __syncwarp();
    const int lastv = sidx[q][found - 1];    // found >= 1 (self qualifies)
    for (int i = found + lane; i < NSAMPLE; i += 32) sidx[q][i] = lastv;
    __syncwarp();

    // ---- Phase 2: gather-max, 2 rows per LDG.128, 2 chains ----
    const char* __restrict__ fbB =
        reinterpret_cast<const char*>(g_fh + (size_t)b * N_PTS * C_OUT) +
        ((lane & 15) * 16);                  // + lo16 folded into base
    const int half = lane >> 4;              // which of 2 rows per load

    const __half2 z2 = __float2half2_rn(0.0f);   // relu outputs >= 0
    __half2 a0[4], a1[4];
    #pragma unroll
    for (int r = 0; r < 4; r++) { a0[r] = z2; a1[r] = z2; }

    #pragma unroll 4
    for (int j = 0; j < NSAMPLE / 4; j++) {
        const int r0 = sidx[q][4 * j + half];
        const int r1 = sidx[q][4 * j + 2 + half];
        const uint4 v0 = *reinterpret_cast<const uint4*>(fbB + r0);
        const uint4 v1 = *reinterpret_cast<const uint4*>(fbB + r1);
        #pragma unroll
        for (int r = 0; r < 4; r++) {
            a0[r] = __hmax2(a0[r], *reinterpret_cast<const __half2*>(&(&v0.x)[r]));
            a1[r] = __hmax2(a1[r], *reinterpret_cast<const __half2*>(&(&v1.x)[r]));
        }
    }

    __half2 m2[4];
    #pragma unroll
    for (int r = 0; r < 4; r++)
        m2[r] = __hmax2(a0[r], a1[r]);

    // combine the two half-warps (each saw half the neighbor slots)
    #pragma unroll
    for (int r = 0; r < 4; r++) {
        const unsigned u = *reinterpret_cast<const unsigned*>(&m2[r]);
        const unsigned o = __shfl_xor_sync(0xffffffffu, u, 16);
        m2[r] = __hmax2(m2[r], *reinterpret_cast<const __half2*>(&o));
    }

    // ---- Phase 3: transpose + coalesced store ----
    // lane covers channels (lane&15)*8 ; half selects which 4 to store
    const int cbase = (lane & 15) * 8 + half * 4;
    const float2 fA = __half22float2(m2[half * 2 + 0]);
    const float2 fB = __half22float2(m2[half * 2 + 1]);
    sout[cbase + 0][q] = fA.x;
    sout[cbase + 1][q] = fA.y;
    sout[cbase + 2][q] = fB.x;
    sout[cbase + 3][q] = fB.y;
    __syncthreads();

    // out shape (B, 128, N); consecutive tid -> consecutive n (64B runs)
    const int nq = tid & 15;
    const int c0 = tid >> 4;                 // 0..31
    float* ob = out + ((size_t)b * C_OUT) * N_PTS + n0 + nq;
    #pragma unroll
    for (int i = 0; i < 4; i++) {
        const int c = c0 + 32 * i;
        ob[(size_t)c * N_PTS] = sout[c][nq];
    }
}

extern "C" void kernel_launch(void* const* d_in, const int* in_sizes, int n_in,
                              void* d_out, int out_size)
{
    const float* x  = (const float*)d_in[0];
    const float* W1 = (const float*)d_in[1];
    const float* b1 = (const float*)d_in[2];
    const float* W2 = (const float*)d_in[3];
    const float* b2 = (const float*)d_in[4];
    float* out = (float*)d_out;

    feat_kernel<<<NPTS_TOTAL / 32, 128>>>(x, W1, b1, W2, b2);   // 512 blocks
    group_max_kernel<<<NPTS_TOTAL / 16, 512>>>(out);            // 1024 blocks
}

// round 15
// speedup vs baseline: 1.0523x; 1.0523x over previous
#include <cuda_runtime.h>
#include <cuda_bf16.h>
#include <cuda_fp16.h>

#define B_DIM 8
#define N_PTS 2048
#define NPTS_TOTAL (B_DIM * N_PTS)
#define C_OUT 128
#define H_DIM 64
#define NSAMPLE 64
#define R2 0.36f

// Scratch (allocation-free rule: __device__ globals)
__device__ __half g_fh[NPTS_TOTAL * C_OUT];  // per-point features, fp16 (4 MB)
__device__ float4 g_xpad[NPTS_TOTAL];        // (x, y, z, x^2+y^2+z^2)

// ---- packed fp32x2 helpers (sm_100+; numerically identical to scalar) -----
__device__ __forceinline__ unsigned long long ffma2(unsigned long long a,
                                                    unsigned long long b,
                                                    unsigned long long c)
{
    unsigned long long d;
    asm("fma.rn.f32x2 %0, %1, %2, %3;" : "=l"(d) : "l"(a), "l"(b), "l"(c));
    return d;
}
__device__ __forceinline__ unsigned long long fadd2(unsigned long long a,
                                                    unsigned long long b)
{
    unsigned long long d;
    asm("add.rn.f32x2 %0, %1, %2;" : "=l"(d) : "l"(a), "l"(b));
    return d;
}
__device__ __forceinline__ unsigned long long bcast2(float h)
{
    unsigned long long d;
    const unsigned hb = __float_as_uint(h);
    asm("mov.b64 %0, {%1, %1};" : "=l"(d) : "r"(hb));
    return d;
}

// ---------------------------------------------------------------------------
// Kernel 1: per-point MLP features.  POINT = LANE + K-SPLIT layout.
// Block = 256 threads = 8 warps, covers 32 points.
//   warp w: channel quarter q = w&3, k-half kh = w>>2 (k in [kh*32, kh*32+32)).
// Each warp: 256 uniform LDS.128 (W2 broadcast) + 512 FFMA2 -> 2x the warps,
// half the per-warp instructions of the unsplit form => latency hiding at
// ~27 warps/SM instead of 13.8.
// kh=1 partials exchanged through smem ([t][q][lane] layout, conflict-free),
// combined with packed f32x2 add by kh=0 warps.
// ---------------------------------------------------------------------------
#define SH1_STRIDE 68
#define SW2F_STRIDE 132

__global__ __launch_bounds__(256)
void feat_kernel(const float* __restrict__ x,
                 const float* __restrict__ W1,
                 const float* __restrict__ b1,
                 const float* __restrict__ W2,
                 const float* __restrict__ b2)
{
    __shared__ float sW2f[H_DIM * SW2F_STRIDE];        // [k][c], 33.8 KB
    __shared__ float sh1[32 * SH1_STRIDE];             // [point][row], 8.7 KB
    __shared__ unsigned long long spart[16 * 4 * 32];  // [t][q][lane], 16 KB
    __shared__ float sW1[H_DIM * 3];
    __shared__ float sb1[H_DIM];
    __shared__ float sb2[C_OUT];

    const int tid = threadIdx.x;
    for (int idx = tid; idx < C_OUT * H_DIM; idx += 256) {
        const int c = idx >> 6, k = idx & 63;
        sW2f[k * SW2F_STRIDE + c] = W2[idx];
    }
    for (int i = tid; i < H_DIM * 3; i += 256) sW1[i] = W1[i];
    for (int i = tid; i < H_DIM;     i += 256) sb1[i] = b1[i];
    for (int i = tid; i < C_OUT;     i += 256) sb2[i] = b2[i];
    __syncthreads();

    const int warp = tid >> 5;
    const int lane = tid & 31;
    const int q    = warp & 3;                 // channel quarter
    const int kh   = warp >> 2;                // k-half
    const int p    = blockIdx.x * 32 + lane;   // this thread's point

    const float x0 = x[p * 3 + 0];
    const float x1 = x[p * 3 + 1];
    const float x2 = x[p * 3 + 2];
    if (warp == 0) {
        // match reference: sq = sum(x*x) left-to-right
        float s = x0 * x0;
        s = s + x1 * x1;
        s = s + x2 * x2;
        g_xpad[p] = make_float4(x0, x1, x2, s);
    }

    // h1: warp w computes rows w*8 .. w*8+7 of point `lane`
    #pragma unroll
    for (int t = 0; t < 8; t++) {
        const int r = warp * 8 + t;
        float v = fmaf(sW1[r * 3 + 2], x2,
                  fmaf(sW1[r * 3 + 1], x1, sW1[r * 3 + 0] * x0)) + sb1[r];
        sh1[lane * SH1_STRIDE + r] = fmaxf(v, 0.0f);
    }
    __syncthreads();

    // 16 packed channel-pair accumulators (channels q*32 + {2t, 2t+1})
    unsigned long long acc[16];
    if (kh == 0) {
        #pragma unroll
        for (int t = 0; t < 16; t++)
            acc[t] = *reinterpret_cast<const unsigned long long*>(
                         &sb2[q * 32 + 2 * t]);
    } else {
        #pragma unroll
        for (int t = 0; t < 16; t++) acc[t] = 0ull;
    }

    const float* h1p = &sh1[lane * SH1_STRIDE + kh * 32];
    const float* w2base = &sW2f[(kh * 32) * SW2F_STRIDE + q * 32];
    #pragma unroll 4
    for (int k4 = 0; k4 < 8; k4++) {
        const float4 h = *reinterpret_cast<const float4*>(&h1p[k4 * 4]);
        #pragma unroll
        for (int kk = 0; kk < 4; kk++) {
            const unsigned long long hh = bcast2((&h.x)[kk]);
            const float* base = w2base + (k4 * 4 + kk) * SW2F_STRIDE;
            #pragma unroll
            for (int g = 0; g < 8; g++) {
                const ulonglong2 w =
                    *reinterpret_cast<const ulonglong2*>(base + g * 4);
                acc[2 * g + 0] = ffma2(w.x, hh, acc[2 * g + 0]);
                acc[2 * g + 1] = ffma2(w.y, hh, acc[2 * g + 1]);
            }
        }
    }

    // exchange: kh=1 stores partials; kh=0 combines, relu, fp16 store
    if (kh == 1) {
        #pragma unroll
        for (int t = 0; t < 16; t++)
            spart[(t * 4 + q) * 32 + lane] = acc[t];
    }
    __syncthreads();
    if (kh == 0) {
        __half* fp = &g_fh[(size_t)p * C_OUT + q * 32];
        #pragma unroll
        for (int t = 0; t < 8; t++) {
            const unsigned long long s0 =
                fadd2(acc[2 * t + 0], spart[((2 * t + 0) * 4 + q) * 32 + lane]);
            const unsigned long long s1 =
                fadd2(acc[2 * t + 1], spart[((2 * t + 1) * 4 + q) * 32 + lane]);
            unsigned l0, h0, l1, h1v;
            asm("mov.b64 {%0, %1}, %2;" : "=r"(l0), "=r"(h0) : "l"(s0));
            asm("mov.b64 {%0, %1}, %2;" : "=r"(l1), "=r"(h1v) : "l"(s1));
            const float f0 = fmaxf(__uint_as_float(l0), 0.0f);
            const float f1 = fmaxf(__uint_as_float(h0), 0.0f);
            const float f2 = fmaxf(__uint_as_float(l1), 0.0f);
            const float f3 = fmaxf(__uint_as_float(h1v), 0.0f);
            __half2 lo = __floats2half2_rn(f0, f1);
            __half2 hi = __floats2half2_rn(f2, f3);
            uint2 v;
            v.x = *reinterpret_cast<unsigned*>(&lo);
            v.y = *reinterpret_cast<unsigned*>(&hi);
            *reinterpret_cast<uint2*>(fp + t * 4) = v;
        }
    }
}

// ---------------------------------------------------------------------------
// Kernel 2 (fused): 512 threads = 16 warps = 16 consecutive queries.
// R9 structure (4 independent load chains, occ 2) + R14's pre-scaled byte
// offsets (no IMAD in the gather address path).
// ---------------------------------------------------------------------------
__global__ __launch_bounds__(512, 2)
void group_max_kernel(float* __restrict__ out)
{
    __shared__ float4 sxb[N_PTS];            // 32 KB
    __shared__ int    sidx[16][NSAMPLE];     // 4 KB  (byte offsets: p*256)
    __shared__ float  sout[C_OUT][17];       // 8.7 KB

    const int tid  = threadIdx.x;
    const int q    = tid >> 5;               // local query 0..15
    const int lane = tid & 31;

    const int b  = blockIdx.x >> 7;          // 128 blocks per batch
    const int n0 = (blockIdx.x & 127) << 4;
    const int n  = n0 + q;

    // ---- Phase 0: stage coords ----
    const float4* __restrict__ xb = g_xpad + b * N_PTS;
    #pragma unroll
    for (int i = tid; i < N_PTS; i += 512) sxb[i] = xb[i];
    __syncthreads();

    const float4 qc = sxb[n];

    // ---- Phase 1: scan (identical classification arithmetic) ----
    int found = 0;
    for (int pb = 0; pb < N_PTS && found < NSAMPLE; pb += 32) {
        const float4 r = sxb[pb + lane];
        const float dot  = fmaf(qc.z, r.z, fmaf(qc.y, r.y, qc.x * r.x));
        const float dist = (qc.w + r.w) - 2.0f * dot;
        const bool  qual = !(dist > R2);
        const unsigned m = __ballot_sync(0xffffffffu, qual);
        const int need = NSAMPLE - found;
        const int rank = __popc(m & ((1u << lane) - 1u));
        const bool take = qual && (rank < need);
        if (take) sidx[q][found + rank] = (pb + lane) << 8;   // byte offset
        found += __popc(__ballot_sync(0xffffffffu, take));
    }
    __syncwarp();
    const int lastv = sidx[q][found - 1];    // found >= 1 (self qualifies)
    for (int i = found + lane; i < NSAMPLE; i += 32) sidx[q][i] = lastv;
    __syncwarp();

    // ---- Phase 2: gather-max, 2 rows per LDG.128, 4 chains ----
    const char* __restrict__ fbB =
        reinterpret_cast<const char*>(g_fh + (size_t)b * N_PTS * C_OUT) +
        ((lane & 15) * 16);                  // + lo16 folded into base
    const int half = lane >> 4;              // which of 2 rows per load

    const __half2 z2 = __float2half2_rn(0.0f);   // relu outputs >= 0
    __half2 a0[4], a1[4], a2[4], a3[4];
    #pragma unroll
    for (int r = 0; r < 4; r++) { a0[r] = z2; a1[r] = z2; a2[r] = z2; a3[r] = z2; }

    #pragma unroll
    for (int j = 0; j < NSAMPLE / 8; j++) {
        const int s = j * 8 + half;
        const int r0 = sidx[q][s + 0];
        const int r1 = sidx[q][s + 2];
        const int r2 = sidx[q][s + 4];
        const int r3 = sidx[q][s + 6];
        const uint4 v0 = *reinterpret_cast<const uint4*>(fbB + r0);
        const uint4 v1 = *reinterpret_cast<const uint4*>(fbB + r1);
        const uint4 v2 = *reinterpret_cast<const uint4*>(fbB + r2);
        const uint4 v3 = *reinterpret_cast<const uint4*>(fbB + r3);
        #pragma unroll
        for (int r = 0; r < 4; r++) {
            a0[r] = __hmax2(a0[r], *reinterpret_cast<const __half2*>(&(&v0.x)[r]));
            a1[r] = __hmax2(a1[r], *reinterpret_cast<const __half2*>(&(&v1.x)[r]));
            a2[r] = __hmax2(a2[r], *reinterpret_cast<const __half2*>(&(&v2.x)[r]));
            a3[r] = __hmax2(a3[r], *reinterpret_cast<const __half2*>(&(&v3.x)[r]));
        }
    }

    __half2 m2[4];
    #pragma unroll
    for (int r = 0; r < 4; r++)
        m2[r] = __hmax2(__hmax2(a0[r], a1[r]), __hmax2(a2[r], a3[r]));

    // combine the two half-warps (each saw half the neighbor slots)
    #pragma unroll
    for (int r = 0; r < 4; r++) {
        const unsigned u = *reinterpret_cast<const unsigned*>(&m2[r]);
        const unsigned o = __shfl_xor_sync(0xffffffffu, u, 16);
        m2[r] = __hmax2(m2[r], *reinterpret_cast<const __half2*>(&o));
    }

    // ---- Phase 3: transpose + coalesced store ----
    const int cbase = (lane & 15) * 8 + half * 4;
    const float2 fA = __half22float2(m2[half * 2 + 0]);
    const float2 fB = __half22float2(m2[half * 2 + 1]);
    sout[cbase + 0][q] = fA.x;
    sout[cbase + 1][q] = fA.y;
    sout[cbase + 2][q] = fB.x;
    sout[cbase + 3][q] = fB.y;
    __syncthreads();

    // out shape (B, 128, N); consecutive tid -> consecutive n (64B runs)
    const int nq = tid & 15;
    const int c0 = tid >> 4;                 // 0..31
    float* ob = out + ((size_t)b * C_OUT) * N_PTS + n0 + nq;
    #pragma unroll
    for (int i = 0; i < 4; i++) {
        const int c = c0 + 32 * i;
        ob[(size_t)c * N_PTS] = sout[c][nq];
    }
}

extern "C" void kernel_launch(void* const* d_in, const int* in_sizes, int n_in,
                              void* d_out, int out_size)
{
    const float* x  = (const float*)d_in[0];
    const float* W1 = (const float*)d_in[1];
    const float* b1 = (const float*)d_in[2];
    const float* W2 = (const float*)d_in[3];
    const float* b2 = (const float*)d_in[4];
    float* out = (float*)d_out;

    feat_kernel<<<NPTS_TOTAL / 32, 256>>>(x, W1, b1, W2, b2);   // 512 blocks
    group_max_kernel<<<NPTS_TOTAL / 16, 512>>>(out);            // 1024 blocks
}